// round 14
// baseline (speedup 1.0000x reference)
#include <cuda_runtime.h>
#include <cstdint>

// QORNN: B=256, T=1024, I=64, H=256, O=16
// Exact integer reformulation (bit-exact vs reference; rel_err 0.0 R2-R10):
//   x_q  = clip(rint(x*128), -128, 127)          int8, scale 1/128
//   W*_q = clip(rint(W*8), -8, 7)                int4-valued int8, scale 1/8
//   z    = (xq@Wiq + hq@Wrq) / 1024              int32 accum, exact in fp32 grid
//   m = relu(|z|+b); h_q = clip(rint(sign(z)*m*128), -128, 127)
// R12 = R11 resubmitted (previous round died to a broker/container flake, not
// a kernel failure). IMMA scan (layouts validated bit-exact in R10) with x
// pre-quantized to int8 (g_XQ) and streamed via a 4-slot cp.async ring.

#define TT 1024
#define NB 256
#define HH 256
#define NI 64
#define NO 16

#define HSTR 68        // h row stride in words (conflict-free B-frag LDS)
#define XSTR 20        // x row stride in words (conflict-free B-frag LDS)

#define NWR (HH * 64)
#define NWI (HH * 16)
#define NWO (NO * 64)
#define NPACK (NWR + NWI + NWO)  // 21504 = 84 * 256

__device__ uint32_t g_WiP[NWI];
__device__ uint32_t g_WrP[NWR];
__device__ uint32_t g_WoP[NWO];
__device__ uint8_t  g_XQ[(size_t)NB * TT * NI + 256];  // +pad for 3-step lead

__device__ __forceinline__ int clampi(int v, int lo, int hi) {
    return v < lo ? lo : (v > hi ? hi : v);
}

__device__ __forceinline__ uint32_t pack4(const float* p) {
    uint32_t w = 0;
#pragma unroll
    for (int j = 0; j < 4; j++) {
        int q = clampi((int)rintf(p[j] * 8.0f), -8, 7);
        w |= ((uint32_t)(uint8_t)(int8_t)q) << (8 * j);
    }
    return w;
}

__global__ __launch_bounds__(256)
void prep_kernel(const float* __restrict__ Wi,
                 const float* __restrict__ Wr,
                 const float* __restrict__ Wo) {
    int i = blockIdx.x * 256 + threadIdx.x;
    if (i < NWR) {
        int row = i >> 6, kw = i & 63;
        g_WrP[i] = pack4(Wr + row * HH + kw * 4);
    } else if (i < NWR + NWI) {
        int j = i - NWR;
        int row = j >> 4, kw = j & 15;
        g_WiP[j] = pack4(Wi + row * NI + kw * 4);
    } else if (i < NPACK) {
        int j = i - NWR - NWI;
        int row = j >> 6, kw = j & 63;
        g_WoP[j] = pack4(Wo + row * HH + kw * 4);
    }
}

// int8 quantize, round-half-even via magic add (exact: v*128 is pow2 scale).
__device__ __forceinline__ int quant8(float v) {
    float tm = fmaf(v, 128.0f, 12582912.0f);        // 2^23 + 2^22
    int q = __float_as_int(tm) - 0x4B400000;        // rint(v*128), half-even
    return max(-128, min(127, q));
}

__device__ __forceinline__ uint32_t q4(float4 v) {
    return (uint32_t)(uint8_t)(int8_t)quant8(v.x)
         | ((uint32_t)(uint8_t)(int8_t)quant8(v.y) << 8)
         | ((uint32_t)(uint8_t)(int8_t)quant8(v.z) << 16)
         | ((uint32_t)(uint8_t)(int8_t)quant8(v.w) << 24);
}

// Pre-quantize all of x: 16 floats -> 16 bytes per thread. Grid 4096 x 256.
__global__ __launch_bounds__(256)
void prep_x_kernel(const float* __restrict__ x) {
    size_t i = ((size_t)blockIdx.x * 256 + threadIdx.x) * 16;
    const float4* xf = (const float4*)(x + i);
    float4 a = xf[0], b = xf[1], c = xf[2], d = xf[3];
    *(uint4*)(g_XQ + i) = make_uint4(q4(a), q4(b), q4(c), q4(d));
}

// modrelu + activation quantization (validated bit-exact R8-R10).
__device__ __forceinline__ int modrelu_q(int z, float bc128) {
    int az = abs(z);                                 // az < 2^19
    float azf = __int_as_float(0x4B000000 + az);     // 2^23 + az, exact
    float t8  = azf * 0.125f;                        // 2^20 + az/8, exact
    float f   = t8 - 1048576.0f;                     // az/8, exact
    float g   = f + bc128;                           // single RN (== ref)
    float m   = fmaxf(g, 0.0f);
    float tm  = m + 12582912.0f;                     // round half-even
    int ni    = __float_as_int(tm) - 0x4B400000;
    int s     = z >> 31;
    int t2    = min(ni, 127 - s);
    int r     = (t2 ^ s) - s;
    int nz    = (z | -z) >> 31;
    return r & nz;
}

// D += A(16x32 s8 row) * B(32x8 s8 col), s32 accum (exact).
__device__ __forceinline__ void mma_s8(int* d, const uint32_t* a,
                                       uint32_t b0, uint32_t b1) {
    asm volatile(
        "mma.sync.aligned.m16n8k32.row.col.s32.s8.s8.s32 "
        "{%0,%1,%2,%3}, {%4,%5,%6,%7}, {%8,%9}, {%0,%1,%2,%3};"
        : "+r"(d[0]), "+r"(d[1]), "+r"(d[2]), "+r"(d[3])
        : "r"(a[0]), "r"(a[1]), "r"(a[2]), "r"(a[3]), "r"(b0), "r"(b1));
}

__device__ __forceinline__ void cp16(void* smem_dst, const void* gsrc) {
    uint32_t s = (uint32_t)__cvta_generic_to_shared(smem_dst);
    asm volatile("cp.async.cg.shared.global [%0], [%1], 16;\n" :: "r"(s), "l"(gsrc));
}
#define CP_COMMIT() asm volatile("cp.async.commit_group;\n" ::: "memory")
#define CP_WAIT2()  asm volatile("cp.async.wait_group 2;\n" ::: "memory")

// Scan: one CTA = 8 batch rows (mma N dim), 256 threads, grid 32, 1 CTA/SM.
__global__ __launch_bounds__(256, 1)
void qornn_kernel(const float* __restrict__ b,
                  float* __restrict__ out) {
    __shared__ uint32_t sh_h[2][8 * HSTR];   // ping-pong h: 8x256 int8 (padded)
    __shared__ uint32_t sh_x[4][8 * XSTR];   // xq ring: 4 steps x 8x64 int8

    const int tid  = threadIdx.x;
    const int w    = tid >> 5;       // warp 0..7 -> units [32w, 32w+32)
    const int lane = tid & 31;
    const int g    = lane >> 2;      // B-column (n) / row-group
    const int tg   = lane & 3;       // k sub-group
    const int r0   = blockIdx.x * 8;

    // A fragments, register-resident (layout validated in R10).
    uint32_t aWr[2][8][4];
    uint32_t aWi[2][2][4];
#pragma unroll
    for (int m = 0; m < 2; m++) {
        const int u0 = w * 32 + m * 16 + g;
#pragma unroll
        for (int kt = 0; kt < 8; kt++) {
            aWr[m][kt][0] = g_WrP[u0 * 64 + kt * 8 + tg];
            aWr[m][kt][1] = g_WrP[(u0 + 8) * 64 + kt * 8 + tg];
            aWr[m][kt][2] = g_WrP[u0 * 64 + kt * 8 + tg + 4];
            aWr[m][kt][3] = g_WrP[(u0 + 8) * 64 + kt * 8 + tg + 4];
        }
#pragma unroll
        for (int kt = 0; kt < 2; kt++) {
            aWi[m][kt][0] = g_WiP[u0 * 16 + kt * 8 + tg];
            aWi[m][kt][1] = g_WiP[(u0 + 8) * 16 + kt * 8 + tg];
            aWi[m][kt][2] = g_WiP[u0 * 16 + kt * 8 + tg + 4];
            aWi[m][kt][3] = g_WiP[(u0 + 8) * 16 + kt * 8 + tg + 4];
        }
    }
    float bb[2][2];
    bb[0][0] = b[w * 32 + g]      * 128.0f;
    bb[0][1] = b[w * 32 + 8 + g]  * 128.0f;
    bb[1][0] = b[w * 32 + 16 + g] * 128.0f;
    bb[1][1] = b[w * 32 + 24 + g] * 128.0f;

    // h0 = 0 (both buffers incl. padding)
    for (int i = tid; i < 2 * 8 * HSTR; i += 256) ((uint32_t*)sh_h)[i] = 0u;

    // x streamer: threads 0..31, (row, 16B-seg) = (tid>>2, tid&3).
    const int sr = tid >> 2;
    const int sseg = tid & 3;
    const uint8_t* xsrc = g_XQ + ((size_t)(r0 + sr) * TT) * NI + sseg * 16;
    if (tid < 32) {
        cp16(&sh_x[0][sr * XSTR + sseg * 4], xsrc + 0 * NI); CP_COMMIT();
        cp16(&sh_x[1][sr * XSTR + sseg * 4], xsrc + 1 * NI); CP_COMMIT();
        cp16(&sh_x[2][sr * XSTR + sseg * 4], xsrc + 2 * NI); CP_COMMIT();
    } else {
        CP_COMMIT(); CP_COMMIT(); CP_COMMIT();   // uniform group accounting
    }
    __syncthreads();

    const int hoff = g * HSTR + tg;
    const int xoff = g * XSTR + tg;

    for (int t = 0; t < TT; t++) {
        const int cur = t & 1;
        const uint32_t* hb = sh_h[cur];

        CP_WAIT2();                           // slot t%4 resident
        const uint32_t* xw = sh_x[t & 3];

        int acc[2][2][4] = {};

        // Recurrent part: K = 256 over sh_h.
#pragma unroll
        for (int kt = 0; kt < 8; kt++) {
            uint32_t b0 = hb[hoff + kt * 8];
            uint32_t b1 = hb[hoff + kt * 8 + 4];
            mma_s8(acc[0][kt & 1], aWr[0][kt], b0, b1);
            mma_s8(acc[1][kt & 1], aWr[1][kt], b0, b1);
        }
        // Input part: K = 64 over ring slot.
#pragma unroll
        for (int kt = 0; kt < 2; kt++) {
            uint32_t b0 = xw[xoff + kt * 8];
            uint32_t b1 = xw[xoff + kt * 8 + 4];
            mma_s8(acc[0][kt], aWi[0][kt], b0, b1);
            mma_s8(acc[1][kt], aWi[1][kt], b0, b1);
        }

        // Refill freed slot with step t+3 (pad in g_XQ covers tail overrun).
        if (tid < 32)
            cp16(&sh_x[(t + 3) & 3][sr * XSTR + sseg * 4],
                 xsrc + (size_t)(t + 3) * NI);
        CP_COMMIT();

        // Epilogue (layout validated in R10).
        int8_t* hn = (int8_t*)sh_h[cur ^ 1];
#pragma unroll
        for (int m = 0; m < 2; m++) {
            const int ub = w * 32 + m * 16 + g;
#pragma unroll
            for (int j = 0; j < 4; j++) {
                int z = acc[m][0][j] + acc[m][1][j];
                int unit = ub + ((j >> 1) << 3);
                int row = 2 * tg + (j & 1);
                hn[row * (HSTR * 4) + unit] = (int8_t)modrelu_q(z, bb[m][j >> 1]);
            }
        }
        __syncthreads();
    }

    // Output head: h_last in buffer 0. 8 rows x 16 outs.
    if (tid < 128) {
        const int row = tid >> 4;
        const int o = tid & 15;
        const uint32_t* hrow = sh_h[0] + row * HSTR;
        int acc = 0;
#pragma unroll
        for (int kw = 0; kw < 64; kw++)
            acc = __dp4a((int)hrow[kw], (int)g_WoP[o * 64 + kw], acc);
        out[(r0 + row) * NO + o] = (float)acc * (1.0f / 1024.0f);
    }
}

extern "C" void kernel_launch(void* const* d_in, const int* in_sizes, int n_in,
                              void* d_out, int out_size) {
    const float* inputs = (const float*)d_in[0];  // [256,1024,64]
    const float* Wi     = (const float*)d_in[1];  // [256,64]
    const float* Wr     = (const float*)d_in[2];  // [256,256]
    const float* Wo     = (const float*)d_in[3];  // [16,256]
    const float* bias   = (const float*)d_in[4];  // [256]
    float* out = (float*)d_out;                   // [256,16]

    prep_kernel<<<(NPACK + 255) / 256, 256>>>(Wi, Wr, Wo);
    prep_x_kernel<<<4096, 256>>>(inputs);
    qornn_kernel<<<NB / 8, 256>>>(bias, out);
}

// round 15
// speedup vs baseline: 1.6816x; 1.6816x over previous
#include <cuda_runtime.h>
#include <cstdint>

// QORNN: B=256, T=1024, I=64, H=256, O=16
// Exact integer reformulation (bit-exact vs reference; rel_err 0.0 R2-R12):
//   x_q  = clip(rint(x*128), -128, 127)          int8, scale 1/128
//   W*_q = clip(rint(W*8), -8, 7)                int4-valued int8, scale 1/8
//   z    = (xq@Wiq + hq@Wrq) / 1024              int32 accum, exact in fp32 grid
//   m = relu(|z|+b); h_q = clip(rint(sign(z)*m*128), -128, 127)
// R13: IMMA scan with REAL latency hiding. R10/R12 ran 2 warps/SMSP with deep
// mma RAW chains -> 83% idle. Now: 512 threads (16 warps = 4/SMSP), ONE
// 16-unit M-tile per warp, 4 independent acc chains (dep depth <=3), no
// cp.async. x staged from pre-quantized g_XQ by warp 15 (1 LDG.128 + 1
// STS.128 per step, 1-step register lead). Fragment layouts/epilogue are
// byte-identical to the R10/R12 validated (rel_err 0.0) code.

#define TT 1024
#define NB 256
#define HH 256
#define NI 64
#define NO 16

#define HSTR 68        // h row stride in words: g*68+tg distinct mod 32
#define XSTR 20        // x row stride in words: g*20+tg distinct mod 32

#define NWR (HH * 64)
#define NWI (HH * 16)
#define NWO (NO * 64)
#define NPACK (NWR + NWI + NWO)  // 21504 = 84 * 256

__device__ uint32_t g_WiP[NWI];
__device__ uint32_t g_WrP[NWR];
__device__ uint32_t g_WoP[NWO];
__device__ uint8_t  g_XQ[(size_t)NB * TT * NI + 256];  // +pad for 2-step lead

__device__ __forceinline__ int clampi(int v, int lo, int hi) {
    return v < lo ? lo : (v > hi ? hi : v);
}

__device__ __forceinline__ uint32_t pack4(const float* p) {
    uint32_t w = 0;
#pragma unroll
    for (int j = 0; j < 4; j++) {
        int q = clampi((int)rintf(p[j] * 8.0f), -8, 7);
        w |= ((uint32_t)(uint8_t)(int8_t)q) << (8 * j);
    }
    return w;
}

__global__ __launch_bounds__(256)
void prep_kernel(const float* __restrict__ Wi,
                 const float* __restrict__ Wr,
                 const float* __restrict__ Wo) {
    int i = blockIdx.x * 256 + threadIdx.x;
    if (i < NWR) {
        int row = i >> 6, kw = i & 63;
        g_WrP[i] = pack4(Wr + row * HH + kw * 4);
    } else if (i < NWR + NWI) {
        int j = i - NWR;
        int row = j >> 4, kw = j & 15;
        g_WiP[j] = pack4(Wi + row * NI + kw * 4);
    } else if (i < NPACK) {
        int j = i - NWR - NWI;
        int row = j >> 6, kw = j & 63;
        g_WoP[j] = pack4(Wo + row * HH + kw * 4);
    }
}

// int8 quantize, round-half-even via magic add (exact: v*128 is pow2 scale).
__device__ __forceinline__ int quant8(float v) {
    float tm = fmaf(v, 128.0f, 12582912.0f);        // 2^23 + 2^22
    int q = __float_as_int(tm) - 0x4B400000;        // rint(v*128), half-even
    return max(-128, min(127, q));
}

__device__ __forceinline__ uint32_t q4(float4 v) {
    return (uint32_t)(uint8_t)(int8_t)quant8(v.x)
         | ((uint32_t)(uint8_t)(int8_t)quant8(v.y) << 8)
         | ((uint32_t)(uint8_t)(int8_t)quant8(v.z) << 16)
         | ((uint32_t)(uint8_t)(int8_t)quant8(v.w) << 24);
}

// Pre-quantize all of x: 16 floats -> 16 bytes per thread. Grid 4096 x 256.
__global__ __launch_bounds__(256)
void prep_x_kernel(const float* __restrict__ x) {
    size_t i = ((size_t)blockIdx.x * 256 + threadIdx.x) * 16;
    const float4* xf = (const float4*)(x + i);
    float4 a = xf[0], b = xf[1], c = xf[2], d = xf[3];
    *(uint4*)(g_XQ + i) = make_uint4(q4(a), q4(b), q4(c), q4(d));
}

// modrelu + activation quantization (validated bit-exact R8-R12).
__device__ __forceinline__ int modrelu_q(int z, float bc128) {
    int az = abs(z);                                 // az < 2^19
    float azf = __int_as_float(0x4B000000 + az);     // 2^23 + az, exact
    float t8  = azf * 0.125f;                        // 2^20 + az/8, exact
    float f   = t8 - 1048576.0f;                     // az/8, exact
    float g   = f + bc128;                           // single RN (== ref)
    float m   = fmaxf(g, 0.0f);
    float tm  = m + 12582912.0f;                     // round half-even
    int ni    = __float_as_int(tm) - 0x4B400000;
    int s     = z >> 31;
    int t2    = min(ni, 127 - s);
    int r     = (t2 ^ s) - s;
    int nz    = (z | -z) >> 31;
    return r & nz;
}

// D += A(16x32 s8 row) * B(32x8 s8 col), s32 accum (exact).
__device__ __forceinline__ void mma_s8(int* d, const uint32_t* a,
                                       uint32_t b0, uint32_t b1) {
    asm volatile(
        "mma.sync.aligned.m16n8k32.row.col.s32.s8.s8.s32 "
        "{%0,%1,%2,%3}, {%4,%5,%6,%7}, {%8,%9}, {%0,%1,%2,%3};"
        : "+r"(d[0]), "+r"(d[1]), "+r"(d[2]), "+r"(d[3])
        : "r"(a[0]), "r"(a[1]), "r"(a[2]), "r"(a[3]), "r"(b0), "r"(b1));
}

// Scan: one CTA = 8 batch rows, 512 threads (16 warps), grid 32, 1 CTA/SM.
// Warp w owns units [16w, 16w+16) = one m16 tile.
__global__ __launch_bounds__(512, 1)
void qornn_kernel(const float* __restrict__ b,
                  float* __restrict__ out) {
    __shared__ uint32_t sh_h[2][8 * HSTR];   // ping-pong h: 8x256 int8 (padded)
    __shared__ uint32_t sh_x[2][8 * XSTR];   // ping-pong xq: 8x64 int8 (padded)

    const int tid  = threadIdx.x;
    const int w    = tid >> 5;       // warp 0..15 -> units [16w, 16w+16)
    const int lane = tid & 31;
    const int g    = lane >> 2;      // B-column (n) / A row-group
    const int tg   = lane & 3;       // k sub-group
    const int r0   = blockIdx.x * 8;
    const int u0   = w * 16 + g;

    // A fragments, register-resident (same per-tile layout validated in R10):
    // a0=(row g, k 4tg..+3), a1=(row g+8), a2=(row g, k+16), a3=(row g+8, k+16)
    uint32_t aWr[8][4];
#pragma unroll
    for (int kt = 0; kt < 8; kt++) {
        aWr[kt][0] = g_WrP[u0 * 64 + kt * 8 + tg];
        aWr[kt][1] = g_WrP[(u0 + 8) * 64 + kt * 8 + tg];
        aWr[kt][2] = g_WrP[u0 * 64 + kt * 8 + tg + 4];
        aWr[kt][3] = g_WrP[(u0 + 8) * 64 + kt * 8 + tg + 4];
    }
    uint32_t aWi[2][4];
#pragma unroll
    for (int kt = 0; kt < 2; kt++) {
        aWi[kt][0] = g_WiP[u0 * 16 + kt * 8 + tg];
        aWi[kt][1] = g_WiP[(u0 + 8) * 16 + kt * 8 + tg];
        aWi[kt][2] = g_WiP[u0 * 16 + kt * 8 + tg + 4];
        aWi[kt][3] = g_WiP[(u0 + 8) * 16 + kt * 8 + tg + 4];
    }
    float bb[2];
    bb[0] = b[u0] * 128.0f;
    bb[1] = b[u0 + 8] * 128.0f;

    // h0 = 0 (both buffers incl. padding)
    for (int i = tid; i < 2 * 8 * HSTR; i += 512) ((uint32_t*)sh_h)[i] = 0u;

    // x stager: warp 15, lane -> (row sr, 16B seg).
    const int sr = lane >> 2;
    const int sseg = lane & 3;
    const uint8_t* xsrc = g_XQ + ((size_t)(r0 + sr) * TT) * NI + sseg * 16;
    uint4 xpre;
    if (w == 15) {
        uint4 v0 = *(const uint4*)xsrc;                       // x(0)
        *(uint4*)&sh_x[0][sr * XSTR + sseg * 4] = v0;
        xpre = *(const uint4*)(xsrc + NI);                    // x(1) lead
    }
    __syncthreads();

    const int hoff = g * HSTR + tg;
    const int xoff = g * XSTR + tg;

    for (int t = 0; t < TT; t++) {
        const int cur = t & 1;
        const uint32_t* hb = sh_h[cur];
        const uint32_t* xw = sh_x[cur];

        // Stager: publish x(t+1) into the idle buffer, prefetch x(t+2).
        // sh_x[cur^1] was last read at step t-1; barrier passed -> safe.
        if (w == 15) {
            *(uint4*)&sh_x[cur ^ 1][sr * XSTR + sseg * 4] = xpre;
            xpre = __ldcs((const uint4*)(xsrc + (size_t)(t + 2) * NI));
        }

        int acc[4][4] = {};   // 4 independent chains, dep depth <= 3

        // Recurrent part: K=256 over sh_h. Chain kt&3 -> deps 4 mmas apart.
#pragma unroll
        for (int kt = 0; kt < 8; kt++) {
            uint32_t b0 = hb[hoff + kt * 8];
            uint32_t b1 = hb[hoff + kt * 8 + 4];
            mma_s8(acc[kt & 3], aWr[kt], b0, b1);
        }
        // Input part: K=64 over sh_x.
#pragma unroll
        for (int kt = 0; kt < 2; kt++) {
            uint32_t b0 = xw[xoff + kt * 8];
            uint32_t b1 = xw[xoff + kt * 8 + 4];
            mma_s8(acc[kt], aWi[kt], b0, b1);
        }

        // Epilogue (mapping validated in R10): frag j -> unit u0+8*(j>>1),
        // batch row 2tg+(j&1).
        int8_t* hn = (int8_t*)sh_h[cur ^ 1];
#pragma unroll
        for (int j = 0; j < 4; j++) {
            int z = (acc[0][j] + acc[1][j]) + (acc[2][j] + acc[3][j]);
            int unit = u0 + ((j >> 1) << 3);
            int row = 2 * tg + (j & 1);
            hn[row * (HSTR * 4) + unit] = (int8_t)modrelu_q(z, bb[j >> 1]);
        }
        __syncthreads();
    }

    // Output head: h_last in buffer 0 (t=1023: cur=1 wrote 0). 8 rows x 16.
    if (tid < 128) {
        const int row = tid >> 4;
        const int o = tid & 15;
        const uint32_t* hrow = sh_h[0] + row * HSTR;
        int acc = 0;
#pragma unroll
        for (int kw = 0; kw < 64; kw++)
            acc = __dp4a((int)hrow[kw], (int)g_WoP[o * 64 + kw], acc);
        out[(r0 + row) * NO + o] = (float)acc * (1.0f / 1024.0f);
    }
}

extern "C" void kernel_launch(void* const* d_in, const int* in_sizes, int n_in,
                              void* d_out, int out_size) {
    const float* inputs = (const float*)d_in[0];  // [256,1024,64]
    const float* Wi     = (const float*)d_in[1];  // [256,64]
    const float* Wr     = (const float*)d_in[2];  // [256,256]
    const float* Wo     = (const float*)d_in[3];  // [16,256]
    const float* bias   = (const float*)d_in[4];  // [256]
    float* out = (float*)d_out;                   // [256,16]

    prep_kernel<<<(NPACK + 255) / 256, 256>>>(Wi, Wr, Wo);
    prep_x_kernel<<<4096, 256>>>(inputs);
    qornn_kernel<<<NB / 8, 512>>>(bias, out);
}

// round 16
// speedup vs baseline: 5.1557x; 3.0659x over previous
#include <cuda_runtime.h>
#include <cstdint>

// QORNN: B=256, T=1024, I=64, H=256, O=16
// Exact integer reformulation (bit-exact vs reference; rel_err 0.0 R2-R13):
//   x_q  = clip(rint(x*128), -128, 127)          int8, scale 1/128
//   W*_q = clip(rint(W*8), -8, 7)                int4-valued int8, scale 1/8
//   z    = (xq@Wiq + hq@Wrq) / 1024              int32 accum, exact in fp32 grid
//   m = relu(|z|+b); h_q = clip(rint(sign(z)*m*128), -128, 127)
// R14: back to the R8 dp4a scan (best: 463.8us). IMMA condemned (R10/12/13 all
// ~3x slower; mma.sync latency-bound on sm_103a). Change vs R8: the per-step x
// LDG+quant8+STS chain (suspected source of the ~300cyc correlated stall,
// fma only 28% busy / issue 47%) is replaced by pre-quantized g_XQ streamed
// through a 4-slot cp.async ring with 3-step lead. Register-free staging; no
// memory scoreboard in any compute warp's pre-barrier path.

#define TT 1024
#define NB 256
#define HH 256
#define NI 64
#define NO 16

#define NWR (HH * 64)
#define NWI (HH * 16)
#define NWO (NO * 64)
#define NPACK (NWR + NWI + NWO)  // 21504 = 84 * 256

__device__ uint32_t g_WiP[NWI];
__device__ uint32_t g_WrP[NWR];
__device__ uint32_t g_WoP[NWO];
__device__ uint8_t  g_XQ[(size_t)NB * TT * NI + 256];  // +pad for 3-step lead

__device__ __forceinline__ int clampi(int v, int lo, int hi) {
    return v < lo ? lo : (v > hi ? hi : v);
}

__device__ __forceinline__ uint32_t pack4(const float* p) {
    uint32_t w = 0;
#pragma unroll
    for (int j = 0; j < 4; j++) {
        int q = clampi((int)rintf(p[j] * 8.0f), -8, 7);
        w |= ((uint32_t)(uint8_t)(int8_t)q) << (8 * j);
    }
    return w;
}

__global__ __launch_bounds__(256)
void prep_kernel(const float* __restrict__ Wi,
                 const float* __restrict__ Wr,
                 const float* __restrict__ Wo) {
    int i = blockIdx.x * 256 + threadIdx.x;
    if (i < NWR) {
        int row = i >> 6, kw = i & 63;
        g_WrP[i] = pack4(Wr + row * HH + kw * 4);
    } else if (i < NWR + NWI) {
        int j = i - NWR;
        int row = j >> 4, kw = j & 15;
        g_WiP[j] = pack4(Wi + row * NI + kw * 4);
    } else if (i < NPACK) {
        int j = i - NWR - NWI;
        int row = j >> 6, kw = j & 63;
        g_WoP[j] = pack4(Wo + row * HH + kw * 4);
    }
}

// int8 quantize, round-half-even via magic add (exact: v*128 is pow2 scale).
__device__ __forceinline__ int quant8(float v) {
    float tm = fmaf(v, 128.0f, 12582912.0f);        // 2^23 + 2^22
    int q = __float_as_int(tm) - 0x4B400000;        // rint(v*128), half-even
    return max(-128, min(127, q));
}

__device__ __forceinline__ uint32_t q4(float4 v) {
    return (uint32_t)(uint8_t)(int8_t)quant8(v.x)
         | ((uint32_t)(uint8_t)(int8_t)quant8(v.y) << 8)
         | ((uint32_t)(uint8_t)(int8_t)quant8(v.z) << 16)
         | ((uint32_t)(uint8_t)(int8_t)quant8(v.w) << 24);
}

// Pre-quantize all of x: 16 floats -> 16 bytes per thread (validated R12/R13).
__global__ __launch_bounds__(256)
void prep_x_kernel(const float* __restrict__ x) {
    size_t i = ((size_t)blockIdx.x * 256 + threadIdx.x) * 16;
    const float4* xf = (const float4*)(x + i);
    float4 a = xf[0], b = xf[1], c = xf[2], d = xf[3];
    *(uint4*)(g_XQ + i) = make_uint4(q4(a), q4(b), q4(c), q4(d));
}

// modrelu + activation quantization (validated bit-exact R8-R13).
__device__ __forceinline__ int modrelu_q(int z, float bc128) {
    int az = abs(z);                                 // az < 2^19
    float azf = __int_as_float(0x4B000000 + az);     // 2^23 + az, exact
    float t8  = azf * 0.125f;                        // 2^20 + az/8, exact
    float f   = t8 - 1048576.0f;                     // az/8, exact
    float g   = f + bc128;                           // single RN (== ref)
    float m   = fmaxf(g, 0.0f);
    float tm  = m + 12582912.0f;                     // round half-even
    int ni    = __float_as_int(tm) - 0x4B400000;
    int s     = z >> 31;
    int t2    = min(ni, 127 - s);
    int r     = (t2 ^ s) - s;
    int nz    = (z | -z) >> 31;
    return r & nz;
}

__device__ __forceinline__ void cp16(void* smem_dst, const void* gsrc) {
    uint32_t s = (uint32_t)__cvta_generic_to_shared(smem_dst);
    asm volatile("cp.async.cg.shared.global [%0], [%1], 16;\n" :: "r"(s), "l"(gsrc));
}
#define CP_COMMIT() asm volatile("cp.async.commit_group;\n" ::: "memory")
#define CP_WAIT2()  asm volatile("cp.async.wait_group 2;\n" ::: "memory")

// Scan: one CTA = one batch row, 256 threads = hidden units, 2 CTAs/SM.
// x streamed from g_XQ via 4-slot cp.async ring (threads 0..3, 16B each).
__global__ __launch_bounds__(256, 2)
void qornn_kernel(const float* __restrict__ b,
                  float* __restrict__ out) {
    __shared__ uint32_t sh_h[2][64];   // ping-pong h, 256 int8 each
    __shared__ uint32_t sh_x[4][16];   // xq ring: 4 steps x 64 int8

    const int tid = threadIdx.x;
    const int r = blockIdx.x;

    uint32_t wr[64];
#pragma unroll
    for (int kw = 0; kw < 64; kw++) wr[kw] = g_WrP[tid * 64 + kw];
    uint32_t wi[16];
#pragma unroll
    for (int i = 0; i < 16; i++) wi[i] = g_WiP[tid * 16 + i];
    const float bc128 = b[tid] * 128.0f;     // exact

    if (tid < 128) ((uint32_t*)sh_h)[tid] = 0u;

    // x streamer: threads 0..3 each own one 16B segment of the 64B step.
    const uint8_t* xsrc = g_XQ + (size_t)r * TT * NI + (tid & 3) * 16;
    if (tid < 4) {
        cp16(&sh_x[0][tid * 4], xsrc + 0 * NI); CP_COMMIT();
        cp16(&sh_x[1][tid * 4], xsrc + 1 * NI); CP_COMMIT();
        cp16(&sh_x[2][tid * 4], xsrc + 2 * NI); CP_COMMIT();
    } else {
        CP_COMMIT(); CP_COMMIT(); CP_COMMIT();   // uniform group accounting
    }
    CP_WAIT2();                                  // slot 0 resident

    // Anti-phase: second co-resident CTA (bid+148) starts ~half a step later
    // so its dp4a block covers the peer's serial chain.
    if (blockIdx.x >= 148) {
        long long c0 = clock64();
        while (clock64() - c0 < 550) { }
    }
    __syncthreads();

    // One step: dp4a x-part (ring slot t&3) + h-part (sh_h[CUR]) -> CUR^1.
#define SCAN_STEP(CUR, T)                                                     \
    {                                                                         \
        int s0 = 0, s1 = 0, s2 = 0, s3 = 0;                                   \
        const uint4* xw = (const uint4*)sh_x[(T) & 3];                        \
        _Pragma("unroll")                                                     \
        for (int k = 0; k < 4; k++) {                                         \
            uint4 v = xw[k];                                                  \
            s0 = __dp4a((int)v.x, (int)wi[4 * k + 0], s0);                    \
            s1 = __dp4a((int)v.y, (int)wi[4 * k + 1], s1);                    \
            s2 = __dp4a((int)v.z, (int)wi[4 * k + 2], s2);                    \
            s3 = __dp4a((int)v.w, (int)wi[4 * k + 3], s3);                    \
        }                                                                     \
        const uint4* hw = (const uint4*)sh_h[CUR];                            \
        _Pragma("unroll")                                                     \
        for (int k = 0; k < 16; k++) {                                        \
            uint4 v = hw[k];                                                  \
            s0 = __dp4a((int)v.x, (int)wr[4 * k + 0], s0);                    \
            s1 = __dp4a((int)v.y, (int)wr[4 * k + 1], s1);                    \
            s2 = __dp4a((int)v.z, (int)wr[4 * k + 2], s2);                    \
            s3 = __dp4a((int)v.w, (int)wr[4 * k + 3], s3);                    \
        }                                                                     \
        const int z = ((s0 + s1) + (s2 + s3));                                \
        ((int8_t*)sh_h[CUR ^ 1])[tid] = (int8_t)modrelu_q(z, bc128);          \
        if (tid < 4)                                                          \
            cp16(&sh_x[((T) + 3) & 3][tid * 4],                               \
                 xsrc + (size_t)((T) + 3) * NI);                              \
        CP_COMMIT();                                                          \
        CP_WAIT2();        /* slot T+1 resident (issued >=2 steps ago) */     \
        __syncthreads();                                                      \
    }

    for (int t = 0; t < TT; t += 2) {
        SCAN_STEP(0, t)
        SCAN_STEP(1, (t + 1))
    }
#undef SCAN_STEP

    // Output head: h_last is in buffer 0 (t=1023: cur=1 wrote nxt=0)
    if (tid < NO) {
        const uint32_t* hrow = sh_h[0];
        int acc = 0;
#pragma unroll
        for (int kw = 0; kw < 64; kw++)
            acc = __dp4a((int)hrow[kw], (int)g_WoP[tid * 64 + kw], acc);
        out[r * NO + tid] = (float)acc * (1.0f / 1024.0f);
    }
}

extern "C" void kernel_launch(void* const* d_in, const int* in_sizes, int n_in,
                              void* d_out, int out_size) {
    const float* inputs = (const float*)d_in[0];  // [256,1024,64]
    const float* Wi     = (const float*)d_in[1];  // [256,64]
    const float* Wr     = (const float*)d_in[2];  // [256,256]
    const float* Wo     = (const float*)d_in[3];  // [16,256]
    const float* bias   = (const float*)d_in[4];  // [256]
    float* out = (float*)d_out;                   // [256,16]

    prep_kernel<<<(NPACK + 255) / 256, 256>>>(Wi, Wr, Wo);
    prep_x_kernel<<<4096, 256>>>(inputs);
    qornn_kernel<<<NB, 256>>>(bias, out);
}